// round 2
// baseline (speedup 1.0000x reference)
#include <cuda_runtime.h>

// SpikeLayer LIF timestep, elementwise over N = 16*56*56*256 = 12,845,056 fp32.
// Inputs (metadata order): impulse, mem, mem_acc, refrac_until, spikecounts.
// Output: 6 stacked tensors [spikes, mem_out, mem_acc_out, refrac_out, counts_out, spiketrain].
//
// Constants from reference: V_THRESH=1.0, TIME=0.5, TAU_REFRAC=2.0 -> refrac reset = 2.5.
// spikes is {0,1}, so:
//   mem_out     = new_mem - spikes
//   counts_out  = spikecounts + spikes
//   spiketrain  = 0.5f * spikes
//   refrac_out  = spikes ? 2.5f : refrac_until

#define TIME_C 0.5f
#define VTH_C 1.0f
#define REFRAC_SET 2.5f

__global__ void __launch_bounds__(256) spike_layer_kernel(
    const float4* __restrict__ impulse,
    const float4* __restrict__ mem,
    const float4* __restrict__ mem_acc,
    const float4* __restrict__ refrac_until,
    const float4* __restrict__ spikecounts,
    float4* __restrict__ out,   // 6 * nvec float4s
    int nvec)
{
    int i = blockIdx.x * blockDim.x + threadIdx.x;
    if (i >= nvec) return;

    float4 imp = impulse[i];
    float4 m   = mem[i];
    float4 ma  = mem_acc[i];
    float4 ru  = refrac_until[i];
    float4 sc  = spikecounts[i];

    float4 spikes, mem_out, ma_out, ru_out, sc_out, st_out;

    #pragma unroll
    for (int c = 0; c < 4; c++) {
        float impv = (&imp.x)[c];
        float mv   = (&m.x)[c];
        float mav  = (&ma.x)[c];
        float ruv  = (&ru.x)[c];
        float scv  = (&sc.x)[c];

        float masked = (ruv > TIME_C) ? 0.0f : impv;
        float new_mem = mv + masked;
        float new_ma  = mav + masked;
        float spk = (new_mem >= VTH_C) ? 1.0f : 0.0f;

        (&spikes.x)[c]  = spk;
        (&mem_out.x)[c] = new_mem - spk;
        (&ma_out.x)[c]  = new_ma;
        (&ru_out.x)[c]  = (spk != 0.0f) ? REFRAC_SET : ruv;
        (&sc_out.x)[c]  = scv + spk;
        (&st_out.x)[c]  = TIME_C * spk;
    }

    out[0 * (size_t)nvec + i] = spikes;
    out[1 * (size_t)nvec + i] = mem_out;
    out[2 * (size_t)nvec + i] = ma_out;
    out[3 * (size_t)nvec + i] = ru_out;
    out[4 * (size_t)nvec + i] = sc_out;
    out[5 * (size_t)nvec + i] = st_out;
}

extern "C" void kernel_launch(void* const* d_in, const int* in_sizes, int n_in,
                              void* d_out, int out_size)
{
    const float* impulse      = (const float*)d_in[0];
    const float* mem          = (const float*)d_in[1];
    const float* mem_acc      = (const float*)d_in[2];
    const float* refrac_until = (const float*)d_in[3];
    const float* spikecounts  = (const float*)d_in[4];

    int n = in_sizes[0];          // 12,845,056 — divisible by 4
    int nvec = n / 4;             // 3,211,264

    int threads = 256;
    int blocks = (nvec + threads - 1) / threads;

    spike_layer_kernel<<<blocks, threads>>>(
        (const float4*)impulse,
        (const float4*)mem,
        (const float4*)mem_acc,
        (const float4*)refrac_until,
        (const float4*)spikecounts,
        (float4*)d_out,
        nvec);
}

// round 3
// speedup vs baseline: 1.0119x; 1.0119x over previous
#include <cuda_runtime.h>

// SpikeLayer LIF timestep, elementwise over N = 16*56*56*256 = 12,845,056 fp32.
// Inputs: impulse, mem, mem_acc, refrac_until, spikecounts.
// Output: 6 stacked tensors [spikes, mem_out, mem_acc_out, refrac_out, counts_out, spiketrain].
//
// spikes ∈ {0,1}:
//   mem_out    = new_mem - spikes
//   counts_out = spikecounts + spikes
//   spiketrain = 0.5f * spikes
//   refrac_out = spikes ? 2.5f : refrac_until
//
// R2 change: 2 float4 per thread, all 10 loads front-batched (MLP_p1 5->10),
// half the blocks (fewer wave transitions). Pure HBM-roofline kernel.

#define TIME_C 0.5f
#define VTH_C 1.0f
#define REFRAC_SET 2.5f
#define VPT 2   // float4 vectors per thread

__global__ void __launch_bounds__(256) spike_layer_kernel(
    const float4* __restrict__ impulse,
    const float4* __restrict__ mem,
    const float4* __restrict__ mem_acc,
    const float4* __restrict__ refrac_until,
    const float4* __restrict__ spikecounts,
    float4* __restrict__ out,   // 6 * nvec float4s
    int nvec)
{
    // Each block covers 256*VPT consecutive float4s; within, thread t handles
    // elements t and t+256 (coalesced across the warp for both).
    int base = blockIdx.x * (256 * VPT) + threadIdx.x;

    float4 imp[VPT], m[VPT], ma[VPT], ru[VPT], sc[VPT];

    // Front-batch all loads for maximum MLP.
    #pragma unroll
    for (int v = 0; v < VPT; v++) {
        int i = base + v * 256;
        if (i < nvec) {
            imp[v] = impulse[i];
            m[v]   = mem[i];
            ma[v]  = mem_acc[i];
            ru[v]  = refrac_until[i];
            sc[v]  = spikecounts[i];
        }
    }

    #pragma unroll
    for (int v = 0; v < VPT; v++) {
        int i = base + v * 256;
        if (i >= nvec) continue;

        float4 spikes, mem_out, ma_out, ru_out, sc_out, st_out;

        #pragma unroll
        for (int c = 0; c < 4; c++) {
            float impv = (&imp[v].x)[c];
            float mv   = (&m[v].x)[c];
            float mav  = (&ma[v].x)[c];
            float ruv  = (&ru[v].x)[c];
            float scv  = (&sc[v].x)[c];

            float masked = (ruv > TIME_C) ? 0.0f : impv;
            float new_mem = mv + masked;
            float spk = (new_mem >= VTH_C) ? 1.0f : 0.0f;

            (&spikes.x)[c]  = spk;
            (&mem_out.x)[c] = new_mem - spk;
            (&ma_out.x)[c]  = mav + masked;
            (&ru_out.x)[c]  = (spk != 0.0f) ? REFRAC_SET : ruv;
            (&sc_out.x)[c]  = scv + spk;
            (&st_out.x)[c]  = TIME_C * spk;
        }

        size_t nv = (size_t)nvec;
        out[0 * nv + i] = spikes;
        out[1 * nv + i] = mem_out;
        out[2 * nv + i] = ma_out;
        out[3 * nv + i] = ru_out;
        out[4 * nv + i] = sc_out;
        out[5 * nv + i] = st_out;
    }
}

extern "C" void kernel_launch(void* const* d_in, const int* in_sizes, int n_in,
                              void* d_out, int out_size)
{
    const float* impulse      = (const float*)d_in[0];
    const float* mem          = (const float*)d_in[1];
    const float* mem_acc      = (const float*)d_in[2];
    const float* refrac_until = (const float*)d_in[3];
    const float* spikecounts  = (const float*)d_in[4];

    int n = in_sizes[0];          // 12,845,056 — divisible by 4
    int nvec = n / 4;             // 3,211,264

    int threads = 256;
    int per_block = threads * VPT;
    int blocks = (nvec + per_block - 1) / per_block;   // 6272

    spike_layer_kernel<<<blocks, threads>>>(
        (const float4*)impulse,
        (const float4*)mem,
        (const float4*)mem_acc,
        (const float4*)refrac_until,
        (const float4*)spikecounts,
        (float4*)d_out,
        nvec);
}